// round 10
// baseline (speedup 1.0000x reference)
#include <cuda_runtime.h>
#include <math.h>

#define N_LI 8192
#define N_RA 2048
#define N_Q  (N_LI + N_RA)
#define M_PTS 2048
#define GRIDW 513
#define TSH 5                     // 32-wide tiles
#define TILES 256
#define TPB 512
#define PITERS (M_PTS / TPB)      // 4
#define LI4 (N_LI / 2)            // 4096 int4 entries (2 queries each)
#define RA4 (N_RA / 2)            // 1024 int4 entries (2 queries each)
#define NSLOW_BLK 8
#define SLOWSEG (N_Q / NSLOW_BLK) // 1280
#define SLOWIT ((SLOWSEG + TPB - 1) / TPB)   // 3
#define QCAP_T 640                // per-tile query cap (mean ~40)
#define SQCAP 96                  // per-slow-block wrapped cap (mean ~5)
#define TWO_R_SLACK 47.6691f      // 2 * 16.5*sqrt(2) + 1.0 slack
#define FINF __int_as_float(0x7f800000)

typedef unsigned long long u64;
__device__ __forceinline__ u64 pack2(float lo, float hi) {
    u64 r; asm("mov.b64 %0, {%1, %2};" : "=l"(r) : "f"(lo), "f"(hi)); return r;
}
#define FMA2(d, a, b, c) asm("fma.rn.f32x2 %0, %1, %2, %3;" : "=l"(d) : "l"(a), "l"(b), "l"(c))
#define UNPK(lo, hi, v)  asm("mov.b64 {%0, %1}, %2;" : "=f"(lo), "=f"(hi) : "l"(v))

// Fused single-launch. SoA smem candidates, f32x2 pair eval, int4 query scan.
// R9 bug fixed: ra int4 scan is RA4/TPB = 2 iterations (was 1 -> half of ra
// queries never scanned -> output 1 wrong).
__global__ __launch_bounds__(TPB, 2) void gauss_map_fused(
    const int* __restrict__ li, const int* __restrict__ ra,
    const float* __restrict__ pts, const int* __restrict__ vox,
    float* __restrict__ out)
{
    __shared__ __align__(16) float s_px[M_PTS + 2];
    __shared__ __align__(16) float s_py[M_PTS + 2];
    __shared__ __align__(16) float s_p2[M_PTS + 2];
    __shared__ int2  s_q[QCAP_T];
    __shared__ float s_mred[16];
    __shared__ int   s_cred[16];
    __shared__ int   s_nc, s_nq;

    const int b = blockIdx.x, tid = threadIdx.x, lane = tid & 31, w = tid >> 5;
    const unsigned FULL = 0xffffffffu;
    const bool is_tile = b < TILES;
    if (tid == 0) { s_nc = 0; s_nq = 0; }

    // ---- single pass over points: d2 vs tile ref cached in registers ----
    const float refx = is_tile ? (float)((b & 15) << TSH) + 15.5f : 0.0f;
    const float refy = is_tile ? (float)((b >> 4) << TSH) + 15.5f : 0.0f;
    float pxr[PITERS], pyr[PITERS], d2r[PITERS];
    float mv = FINF;
    int cntw = 0;
    #pragma unroll
    for (int it = 0; it < PITERS; it++) {
        int i = it * TPB + tid;
        bool pass = fabsf(pts[i * 5 + 4]) > 0.1f;
        cntw += __popc(__ballot_sync(FULL, pass));
        float px = 0.f, py = 0.f, d2 = FINF;
        if (pass) {
            px = (float)vox[i * 3 + 1];
            py = (float)vox[i * 3 + 2];
            float dx = px - refx, dy = py - refy;
            d2 = fmaf(dx, dx, dy * dy);
        }
        pxr[it] = px; pyr[it] = py; d2r[it] = d2;
        mv = fminf(mv, d2);
    }
    #pragma unroll
    for (int o = 16; o; o >>= 1) mv = fminf(mv, __shfl_xor_sync(FULL, mv, o));
    if (lane == 0) { s_mred[w] = mv; s_cred[w] = cntw; }
    __syncthreads();

    float m = s_mred[0]; int tot = s_cred[0];
    #pragma unroll
    for (int i = 1; i < 16; i++) { m = fminf(m, s_mred[i]); tot += s_cred[i]; }
    const bool active = tot > 1;             // reference: use = sum(dy_mask) > 1
    float thr = 3.9e38f;                     // slow blocks keep all dynamic pts
    if (is_tile) {
        float u = sqrtf(m) + TWO_R_SLACK;    // keep iff d(ref,c) <= sqrt(Umin)+2R+1
        thr = u * u;
    }

    // ---- register-only compaction (rare shared atomic) ----
    if (active) {
        #pragma unroll
        for (int it = 0; it < PITERS; it++) {
            if (d2r[it] <= thr) {            // INF for non-dynamic never passes
                int idx = atomicAdd(&s_nc, 1);
                float px = pxr[it], py = pyr[it];
                s_px[idx] = px; s_py[idx] = py; s_p2[idx] = fmaf(px, px, py * py);
            }
        }
    }

    // ---- query scan: int4 loads (2 queries each) ----
    if (is_tile) {
        const int4* __restrict__ li4 = (const int4*)li;   // LI4 = 4096 entries
        const int4* __restrict__ ra4 = (const int4*)ra;   // RA4 = 1024 entries
        #pragma unroll
        for (int it = 0; it < LI4 / TPB; it++) {          // 8 iters
            int i = it * TPB + tid;
            int4 e = li4[i];
            if (((((e.y >> TSH) << 4) | (e.x >> TSH)) == b) && e.x && e.y) {
                int idx = atomicAdd(&s_nq, 1);
                if (idx < QCAP_T) s_q[idx] = make_int2(2 * i, e.x | (e.y << 16));
            }
            if (((((e.w >> TSH) << 4) | (e.z >> TSH)) == b) && e.z && e.w) {
                int idx = atomicAdd(&s_nq, 1);
                if (idx < QCAP_T) s_q[idx] = make_int2(2 * i + 1, e.z | (e.w << 16));
            }
        }
        #pragma unroll
        for (int it = 0; it < RA4 / TPB; it++) {          // 2 iters (R9 fix)
            int i = it * TPB + tid;
            int4 e = ra4[i];
            if (((((e.y >> TSH) << 4) | (e.x >> TSH)) == b) && e.x && e.y) {
                int idx = atomicAdd(&s_nq, 1);
                if (idx < QCAP_T) s_q[idx] = make_int2(N_LI + 2 * i, e.x | (e.y << 16));
            }
            if (((((e.w >> TSH) << 4) | (e.z >> TSH)) == b) && e.z && e.w) {
                int idx = atomicAdd(&s_nq, 1);
                if (idx < QCAP_T) s_q[idx] = make_int2(N_LI + 2 * i + 1, e.z | (e.w << 16));
            }
        }
    } else {
        const int sb = b - TILES;
        #pragma unroll
        for (int it = 0; it < SLOWIT; it++) {
            int r = it * TPB + tid;
            if (r < SLOWSEG) {
                int q = sb * SLOWSEG + r;
                const int* p = (q < N_LI) ? (li + 2 * q) : (ra + 2 * (q - N_LI));
                int x = p[0], y = p[1];
                if (x == 0 || y == 0) {
                    int idx = atomicAdd(&s_nq, 1);
                    if (idx < SQCAP) s_q[idx] = make_int2(q, x | (y << 16));
                }
            }
        }
    }
    __syncthreads();
    const int cn = active ? s_nc : 0;
    if (tid < 2) {                            // sentinel pads for pair eval
        s_px[cn + tid] = 1.0e9f; s_py[cn + tid] = 1.0e9f; s_p2[cn + tid] = 2.0e18f;
    }
    __syncthreads();
    const int qn = min(s_nq, is_tile ? QCAP_T : SQCAP);
    if (qn == 0) return;

    if (is_tile) {
        // ---- pair eval: 64 query slots x 8 pair-slices (f32x2) ----
        const int s = tid & 7, qslot = tid >> 3;
        const int cnp = (cn + 1) & ~1;        // even; sentinels cover the pad
        for (int q0 = 0; q0 < qn; q0 += 64) {
            if (q0 + (w << 2) >= qn) continue;    // whole warp empty: skip
            const int qi = q0 + qslot;
            const bool have = qi < qn;
            int2 e = have ? s_q[qi] : make_int2(0, 0);
            const unsigned xy = (unsigned)e.y;
            const int x = (int)(xy & 0xffffu), y = (int)(xy >> 16);
            // INDEX_SHIFT: dim0 {0,-1,+1} (a=j%3), dim1 {0,+1,-1} (b=j/3); no wrap
            const float xa0 = (float)x, xa1 = (float)(x - 1), xa2 = (float)(x + 1);
            const float yb0 = (float)y, yb1 = (float)(y + 1), yb2 = (float)(y - 1);
            const u64 n2x[3] = { pack2(-2.f * xa0, -2.f * xa0),
                                 pack2(-2.f * xa1, -2.f * xa1),
                                 pack2(-2.f * xa2, -2.f * xa2) };
            const u64 n2y[3] = { pack2(-2.f * yb0, -2.f * yb0),
                                 pack2(-2.f * yb1, -2.f * yb1),
                                 pack2(-2.f * yb2, -2.f * yb2) };
            float mn[9];
            #pragma unroll
            for (int j = 0; j < 9; j++) mn[j] = 3.0e38f;
            const int cl = have ? cnp : 0;
            #pragma unroll 2
            for (int k2 = s * 2; k2 < cl; k2 += 16) {
                const u64 cx = *(const u64*)(s_px + k2);   // LDS.64, k2 even
                const u64 cy = *(const u64*)(s_py + k2);
                const u64 cz = *(const u64*)(s_p2 + k2);
                u64 w0, w1, w2;
                FMA2(w0, n2y[0], cy, cz);
                FMA2(w1, n2y[1], cy, cz);
                FMA2(w2, n2y[2], cy, cz);
                const u64 wb[3] = {w0, w1, w2};
                #pragma unroll
                for (int bb = 0; bb < 3; bb++) {
                    #pragma unroll
                    for (int aa = 0; aa < 3; aa++) {
                        u64 t; float tl, th;
                        FMA2(t, n2x[aa], cx, wb[bb]);
                        UNPK(tl, th, t);
                        mn[bb * 3 + aa] = fminf(mn[bb * 3 + aa], fminf(tl, th));
                    }
                }
            }
            #pragma unroll
            for (int j = 0; j < 9; j++) {                // reduce over 8 slices
                float v = mn[j];
                v = fminf(v, __shfl_xor_sync(FULL, v, 1));
                v = fminf(v, __shfl_xor_sync(FULL, v, 2));
                v = fminf(v, __shfl_xor_sync(FULL, v, 4));
                mn[j] = v;
            }
            if (s == 0 && have) {
                const float x2[3] = {xa0 * xa0, xa1 * xa1, xa2 * xa2};
                const float y2[3] = {yb0 * yb0, yb1 * yb1, yb2 * yb2};
                float* o = out + (size_t)e.x * 9;
                #pragma unroll
                for (int j = 0; j < 9; j++) {
                    float d2 = mn[j] + x2[j % 3] + y2[j / 3];
                    o[j] = active ? 0.01f * sqrtf(fmaxf(d2, 0.0f)) : 0.0f;
                }
            }
        }
    } else {
        // ---- slow path: one warp per wrapped query, full candidate list ----
        for (int si = w; si < qn; si += 16) {
            const int2 e = s_q[si];
            const unsigned xy = (unsigned)e.y;
            const int x = (int)(xy & 0xffffu), y = (int)(xy >> 16);
            int xm = x - 1; if (xm < 0)      xm += GRIDW;
            int xp = x + 1; if (xp >= GRIDW) xp -= GRIDW;
            int ym = y - 1; if (ym < 0)      ym += GRIDW;
            int yp = y + 1; if (yp >= GRIDW) yp -= GRIDW;
            const float xa0 = (float)x,  xa1 = (float)xm, xa2 = (float)xp;
            const float yb0 = (float)y,  yb1 = (float)yp, yb2 = (float)ym;
            const float n2x0 = -2.f * xa0, n2x1 = -2.f * xa1, n2x2 = -2.f * xa2;
            const float n2y0 = -2.f * yb0, n2y1 = -2.f * yb1, n2y2 = -2.f * yb2;
            float mn[9];
            #pragma unroll
            for (int j = 0; j < 9; j++) mn[j] = 3.0e38f;
            for (int k = lane; k < cn; k += 32) {
                const float cxx = s_px[k], cyy = s_py[k], czz = s_p2[k];
                const float w0 = fmaf(n2y0, cyy, czz);
                const float w1 = fmaf(n2y1, cyy, czz);
                const float w2 = fmaf(n2y2, cyy, czz);
                mn[0] = fminf(mn[0], fmaf(n2x0, cxx, w0));
                mn[1] = fminf(mn[1], fmaf(n2x1, cxx, w0));
                mn[2] = fminf(mn[2], fmaf(n2x2, cxx, w0));
                mn[3] = fminf(mn[3], fmaf(n2x0, cxx, w1));
                mn[4] = fminf(mn[4], fmaf(n2x1, cxx, w1));
                mn[5] = fminf(mn[5], fmaf(n2x2, cxx, w1));
                mn[6] = fminf(mn[6], fmaf(n2x0, cxx, w2));
                mn[7] = fminf(mn[7], fmaf(n2x1, cxx, w2));
                mn[8] = fminf(mn[8], fmaf(n2x2, cxx, w2));
            }
            #pragma unroll
            for (int j = 0; j < 9; j++) {
                float v = mn[j];
                #pragma unroll
                for (int o = 16; o; o >>= 1) v = fminf(v, __shfl_xor_sync(FULL, v, o));
                mn[j] = v;
            }
            if (lane == 0) {
                const float x2[3] = {xa0 * xa0, xa1 * xa1, xa2 * xa2};
                const float y2[3] = {yb0 * yb0, yb1 * yb1, yb2 * yb2};
                float* o = out + (size_t)e.x * 9;
                #pragma unroll
                for (int j = 0; j < 9; j++) {
                    float d2 = mn[j] + x2[j % 3] + y2[j / 3];
                    o[j] = active ? 0.01f * sqrtf(fmaxf(d2, 0.0f)) : 0.0f;
                }
            }
        }
    }
}

extern "C" void kernel_launch(void* const* d_in, const int* in_sizes, int n_in,
                              void* d_out, int out_size) {
    const int*   li  = (const int*)d_in[0];
    const int*   ra  = (const int*)d_in[1];
    const float* pts = (const float*)d_in[2];
    const int*   vox = (const int*)d_in[3];
    float* out = (float*)d_out;
    gauss_map_fused<<<TILES + NSLOW_BLK, TPB>>>(li, ra, pts, vox, out);
}